// round 15
// baseline (speedup 1.0000x reference)
#include <cuda_runtime.h>
#include <cuda_fp16.h>
#include <math.h>

// ---------------- problem constants ----------------
#define D512 512
#define NH   8
#define DH   64
#define BMAX 32
#define NMAX 16384
#define MROWS (NMAX + BMAX)   // 16416

// ---------------- fp32 scratch ----------------
__device__ __align__(256) float g_xc[MROWS * D512];
__device__ __align__(256) float g_ao[MROWS * D512];
__device__ __align__(256) float g_hn[MROWS * D512];
__device__ __align__(256) float g_f [MROWS * D512];
__device__ int g_starts[BMAX + 1];

// ---------------- fp16 split planes (u32 = 2 fp16, low half = even k) ----------------
__device__ __align__(256) unsigned g_xch[MROWS * 256], g_xcl[MROWS * 256];
__device__ __align__(256) unsigned g_qh [MROWS * 256], g_ql [MROWS * 256];
__device__ __align__(256) unsigned g_kh [MROWS * 256], g_kl [MROWS * 256];
__device__ __align__(256) unsigned g_vh [MROWS * 256], g_vl [MROWS * 256];
__device__ __align__(256) unsigned g_ath[MROWS * 256], g_atl[MROWS * 256];
__device__ __align__(256) unsigned g_hnh[MROWS * 256], g_hnl[MROWS * 256];
__device__ __align__(256) unsigned g_th [MROWS * 512], g_tl [MROWS * 512];
// weight hi planes only (2-term GEMM), pre-paired along k: u32[k2*N+n] = {W[2k2][n], W[2k2+1][n]}
#define WQ_OFF 0
#define WK_OFF 131072
#define WV_OFF 262144
#define WO_OFF 393216
#define W1_OFF 524288
#define W2_OFF 786432
#define WTOT   1048576
__device__ __align__(256) unsigned g_wh[WTOT];

// ---------------- helpers ----------------
__device__ __forceinline__ void splitpair(float x, float y, unsigned& h, unsigned& l) {
    __half hx = __float2half_rn(x);
    __half hy = __float2half_rn(y);
    __half lx = __float2half_rn(x - __half2float(hx));
    __half ly = __float2half_rn(y - __half2float(hy));
    __half2 hh = __halves2half2(hx, hy);
    __half2 ll = __halves2half2(lx, ly);
    h = *(unsigned*)&hh; l = *(unsigned*)&ll;
}
__device__ __forceinline__ unsigned hipair(float x, float y) {
    __half2 hh = __halves2half2(__float2half_rn(x), __float2half_rn(y));
    return *(unsigned*)&hh;
}
__device__ __forceinline__ void mma16(float* c, const unsigned* a, const unsigned* b) {
    asm volatile(
        "mma.sync.aligned.m16n8k16.row.col.f32.f16.f16.f32 "
        "{%0,%1,%2,%3}, {%4,%5,%6,%7}, {%8,%9}, {%0,%1,%2,%3};"
        : "+f"(c[0]), "+f"(c[1]), "+f"(c[2]), "+f"(c[3])
        : "r"(a[0]), "r"(a[1]), "r"(a[2]), "r"(a[3]), "r"(b[0]), "r"(b[1]));
}
__device__ __forceinline__ void ldm4(unsigned* d, unsigned a) {
    asm volatile("ldmatrix.sync.aligned.m8n8.x4.shared.b16 {%0,%1,%2,%3}, [%4];"
        : "=r"(d[0]), "=r"(d[1]), "=r"(d[2]), "=r"(d[3]) : "r"(a));
}
__device__ __forceinline__ void ldm4t(unsigned* d, unsigned a) {
    asm volatile("ldmatrix.sync.aligned.m8n8.x4.trans.shared.b16 {%0,%1,%2,%3}, [%4];"
        : "=r"(d[0]), "=r"(d[1]), "=r"(d[2]), "=r"(d[3]) : "r"(a));
}
__device__ __forceinline__ void cpa16(unsigned dst, const void* src, int sz) {
    asm volatile("cp.async.cg.shared.global [%0], [%1], 16, %2;"
        :: "r"(dst), "l"(src), "r"(sz));
}
#define CP_COMMIT() asm volatile("cp.async.commit_group;")
#define CP_WAIT0()  asm volatile("cp.async.wait_group 0;")
#define CP_WAIT1()  asm volatile("cp.async.wait_group 1;")

// ---------------- starts ----------------
__global__ void k_starts(const int* __restrict__ batch, int N, int B) {
    int b = threadIdx.x;
    if (b > B) return;
    int lo = 0, hi = N;
    while (lo < hi) {
        int mid = (lo + hi) >> 1;
        if (batch[mid] < b) lo = mid + 1; else hi = mid;
    }
    g_starts[b] = lo;
}

// ---------------- weight split (hi plane only, pre-paired along k) ----------------
__global__ void k_splitW(const float* __restrict__ Wq, const float* __restrict__ Wk,
                         const float* __restrict__ Wv, const float* __restrict__ Wo,
                         const float* __restrict__ W1, const float* __restrict__ W2) {
    int t = blockIdx.x * 256 + threadIdx.x;
    if (t >= WTOT) return;
    const float* W; int rel; bool n1024 = false;
    if      (t < WK_OFF) { W = Wq; rel = t; }
    else if (t < WV_OFF) { W = Wk; rel = t - WK_OFF; }
    else if (t < WO_OFF) { W = Wv; rel = t - WV_OFF; }
    else if (t < W1_OFF) { W = Wo; rel = t - WO_OFF; }
    else if (t < W2_OFF) { W = W1; rel = t - W1_OFF; n1024 = true; }
    else                 { W = W2; rel = t - W2_OFF; }
    int N = n1024 ? 1024 : 512;
    int k2 = n1024 ? (rel >> 10) : (rel >> 9);
    int n  = rel & (N - 1);
    g_wh[t] = hipair(W[(size_t)(2 * k2) * N + n], W[(size_t)(2 * k2 + 1) * N + n]);
}

// ---------------- compact input [x; CLS] -> fp32 + planes ----------------
__global__ void k_xc(const float* __restrict__ x, const float* __restrict__ cls, int N) {
    int row = blockIdx.x;
    int tid = threadIdx.x;
    const float* src = (row < N) ? (x + (size_t)row * D512)
                                 : (cls + (size_t)(row - N) * D512);
    float4 v = ((const float4*)src)[tid];
    ((float4*)(g_xc + (size_t)row * D512))[tid] = v;
    unsigned h0, l0, h1, l1;
    splitpair(v.x, v.y, h0, l0);
    splitpair(v.z, v.w, h1, l1);
    size_t p = (size_t)row * 256 + 2 * tid;
    g_xch[p] = h0; g_xch[p + 1] = h1;
    g_xcl[p] = l0; g_xcl[p + 1] = l1;
}

// ---------------- pipelined 2-term fp16 GEMM ----------------
// A planes hi+lo [M][K/2] u32, B hi plane pre-paired [K/2][N] u32.
// C = (Ah+Al)·Bh + bias [+res] [relu]; 128x128 tile, K-chunk 32, 2-stage cp.async.
#define STGU 7296                 // A 2*2560 + B 2176
#define A_LO 2560
#define B_HI 5120
#define GEMM_SMEM_BYTES (2 * STGU * 4)   // 58368

template<bool RELU, bool HASRES, bool WF32, bool WPL>
__device__ __forceinline__ void gemm_core(
    const unsigned* __restrict__ Ah, const unsigned* __restrict__ Al,
    const unsigned* __restrict__ Bh,
    const float* __restrict__ bias, const float* __restrict__ res,
    float* __restrict__ C, unsigned* __restrict__ CPh, unsigned* __restrict__ CPl,
    int M, int N, int K)
{
    extern __shared__ unsigned sm[];
    const int Ku = K >> 1;
    int tid = threadIdx.x, lane = tid & 31, warp = tid >> 5;
    int wm = warp >> 2, wn = warp & 3;
    int brow = blockIdx.y * 128, bcol = blockIdx.x * 128;
    unsigned smb = (unsigned)__cvta_generic_to_shared(sm);

    float acc[4][4][4];
#pragma unroll
    for (int mt = 0; mt < 4; mt++)
#pragma unroll
        for (int nt = 0; nt < 4; nt++)
#pragma unroll
            for (int i = 0; i < 4; i++) acc[mt][nt][i] = 0.f;

    int arow = tid >> 2, aq = tid & 3;
    int bk2  = tid >> 5, bq = tid & 31;
    int ag0 = brow + arow, ag1 = ag0 + 64;
    int as0 = (ag0 < M) ? 16 : 0, as1 = (ag1 < M) ? 16 : 0;
    const unsigned* Ar0h = Ah + (size_t)((ag0 < M) ? ag0 : 0) * Ku + aq * 4;
    const unsigned* Ar1h = Ah + (size_t)((ag1 < M) ? ag1 : 0) * Ku + aq * 4;
    const unsigned* Ar0l = Al + (size_t)((ag0 < M) ? ag0 : 0) * Ku + aq * 4;
    const unsigned* Ar1l = Al + (size_t)((ag1 < M) ? ag1 : 0) * Ku + aq * 4;
    const unsigned* B0h = Bh + (size_t)bk2 * N + bcol + bq * 4;
    const unsigned* B1h = Bh + (size_t)(bk2 + 8) * N + bcol + bq * 4;
    unsigned dA0 = smb + 4 * (arow * 20 + aq * 4);
    unsigned dA1 = smb + 4 * ((arow + 64) * 20 + aq * 4);
    unsigned dB0 = smb + 4 * (B_HI + bk2 * 136 + bq * 4);
    unsigned dB1 = smb + 4 * (B_HI + (bk2 + 8) * 136 + bq * 4);

    int nch = K >> 5;

    auto issue = [&](int st, int ch) {
        unsigned so = st * (STGU * 4);
        int ko = ch * 16;
        cpa16(so + dA0,            Ar0h + ko, as0);
        cpa16(so + dA1,            Ar1h + ko, as1);
        cpa16(so + dA0 + A_LO * 4, Ar0l + ko, as0);
        cpa16(so + dA1 + A_LO * 4, Ar1l + ko, as1);
        size_t bko = (size_t)ko * N;
        cpa16(so + dB0, B0h + bko, 16);
        cpa16(so + dB1, B1h + bko, 16);
        CP_COMMIT();
    };

    issue(0, 0);

    int r = lane >> 2, cl = lane & 3;
    int lrow = lane & 15, kq = lane >> 4;
    for (int ch = 0; ch < nch; ch++) {
        CP_WAIT0();
        __syncthreads();
        if (ch + 1 < nch) issue((ch + 1) & 1, ch + 1);
        int base = (ch & 1) * STGU;
#pragma unroll
        for (int s = 0; s < 2; s++) {
            unsigned ah[4][4], al[4][4];
#pragma unroll
            for (int mt = 0; mt < 4; mt++) {
                unsigned ao_ = smb + 4 * (base + (wm * 64 + mt * 16 + lrow) * 20 + s * 8 + kq * 4);
                ldm4(ah[mt], ao_);
                ldm4(al[mt], ao_ + A_LO * 4);
            }
            unsigned bhf[4][2];
#pragma unroll
            for (int nt = 0; nt < 4; nt++) {
                int o = base + B_HI + (s * 8 + cl) * 136 + wn * 32 + nt * 8 + r;
                bhf[nt][0] = sm[o];  bhf[nt][1] = sm[o + 4 * 136];
            }
#pragma unroll
            for (int mt = 0; mt < 4; mt++)
#pragma unroll
                for (int nt = 0; nt < 4; nt++) {
                    mma16(acc[mt][nt], ah[mt], bhf[nt]);
                    mma16(acc[mt][nt], al[mt], bhf[nt]);
                }
        }
        __syncthreads();
    }

#pragma unroll
    for (int mt = 0; mt < 4; mt++) {
        int row0 = brow + wm * 64 + mt * 16 + r;
        int row1 = row0 + 8;
#pragma unroll
        for (int nt = 0; nt < 4; nt++) {
            int col = bcol + wn * 32 + nt * 8 + cl * 2;
            float2 bb = *(const float2*)(bias + col);
            const float* c = acc[mt][nt];
#pragma unroll
            for (int half = 0; half < 2; half++) {
                int row = half ? row1 : row0;
                if (row < M) {
                    float v0 = c[2 * half] + bb.x, v1 = c[2 * half + 1] + bb.y;
                    if (HASRES) {
                        float2 rv = *(const float2*)(res + (size_t)row * N + col);
                        v0 += rv.x; v1 += rv.y;
                    }
                    if (RELU) { v0 = fmaxf(v0, 0.f); v1 = fmaxf(v1, 0.f); }
                    if (WF32)
                        *(float2*)(C + (size_t)row * N + col) = make_float2(v0, v1);
                    if (WPL) {
                        unsigned h, l;
                        splitpair(v0, v1, h, l);
                        size_t p = ((size_t)row * N + col) >> 1;
                        CPh[p] = h; CPl[p] = l;
                    }
                }
            }
        }
    }
}

__global__ void __launch_bounds__(256, 2) k_qkv(
    const float* __restrict__ bq, const float* __restrict__ bk,
    const float* __restrict__ bv, int M)
{
    const unsigned* Bh; const float* bias; unsigned* Ph; unsigned* Pl;
    if (blockIdx.z == 0)      { Bh = g_wh + WQ_OFF; bias = bq; Ph = g_qh; Pl = g_ql; }
    else if (blockIdx.z == 1) { Bh = g_wh + WK_OFF; bias = bk; Ph = g_kh; Pl = g_kl; }
    else                      { Bh = g_wh + WV_OFF; bias = bv; Ph = g_vh; Pl = g_vl; }
    gemm_core<false, false, false, true>(g_xch, g_xcl, Bh, bias,
        (const float*)0, (float*)0, Ph, Pl, M, 512, 512);
}
__global__ void __launch_bounds__(256, 2) k_wo(const float* __restrict__ bo, int M) {
    gemm_core<false, true, true, false>(g_ath, g_atl, g_wh + WO_OFF,
        bo, g_xc, g_ao, (unsigned*)0, (unsigned*)0, M, 512, 512);
}
__global__ void __launch_bounds__(256, 2) k_ffn1(const float* __restrict__ b1, int M) {
    gemm_core<true, false, false, true>(g_hnh, g_hnl, g_wh + W1_OFF,
        b1, (const float*)0, (float*)0, g_th, g_tl, M, 1024, 512);
}
__global__ void __launch_bounds__(256, 2) k_ffn2(const float* __restrict__ b2, int M) {
    gemm_core<false, true, true, false>(g_th, g_tl, g_wh + W2_OFF,
        b2, g_hn, g_f, (unsigned*)0, (unsigned*)0, M, 512, 1024);
}

// ---------------- fp16 tensor-core flash attention, double-buffered ----------------
// stage (9216 u32): [0..2304) KsHi [2304..4608) KsLo [4608..6912) VsHi [6912..9216) VsLo
// rows [0..63] x 32 u32 dim-pairs, stride 36 (conflict-free). Two stages = 73728 B dynamic.
#define AST 36
#define A_STG 9216
#define KL_OFF 2304
#define VH_OFF 4608
#define VL_OFF 6912
#define ATT_SMEM (2 * A_STG * 4)   // 73728

__global__ void __launch_bounds__(128) k_attn_mma(int N) {
    extern __shared__ unsigned sm[];
    int b = blockIdx.z, h = blockIdx.y, qt = blockIdx.x;
    int stt = g_starts[b];
    int cnt = g_starts[b + 1] - stt;
    int Lb = cnt + 1;
    if (qt * 64 >= Lb) return;
    int tid = threadIdx.x, lane = tid & 31, warp = tid >> 5;
    int lr = lane >> 2, lc = lane & 3;
    unsigned smb = (unsigned)__cvta_generic_to_shared(sm);

    int srow = tid >> 1, shalf = (tid & 1) * 16;
    unsigned dRow = smb + 4 * (srow * AST + shalf);     // stage-0 row address

    // ---- stage Q planes into stage-0 K region, extract a-frags ----
    {
        int qi = qt * 64 + srow;
        int grow = (qi < cnt) ? stt + qi : N + b;
        size_t so = (size_t)grow * 256 + h * 32 + shalf;
#pragma unroll
        for (int i = 0; i < 4; i++) {
            cpa16(dRow + 16 * i,               g_qh + so + 4 * i, 16);
            cpa16(dRow + 16 * i + KL_OFF * 4,  g_ql + so + 4 * i, 16);
        }
        CP_COMMIT(); CP_WAIT0();
    }
    __syncthreads();
    unsigned qh[4][4], qlo[4][4];
    {
        int rq = warp * 16 + lr;
#pragma unroll
        for (int ks = 0; ks < 4; ks++) {
            int c0 = ks * 8 + lc;
            qh[ks][0]  = sm[rq*AST + c0];               qh[ks][1]  = sm[(rq+8)*AST + c0];
            qh[ks][2]  = sm[rq*AST + c0 + 4];           qh[ks][3]  = sm[(rq+8)*AST + c0 + 4];
            qlo[ks][0] = sm[KL_OFF + rq*AST + c0];      qlo[ks][1] = sm[KL_OFF + (rq+8)*AST + c0];
            qlo[ks][2] = sm[KL_OFF + rq*AST + c0 + 4];  qlo[ks][3] = sm[KL_OFF + (rq+8)*AST + c0 + 4];
        }
    }
    __syncthreads();

    auto issue = [&](int stg_i, int kt) {
        int ki = kt * 64 + srow;
        int grow = (ki < cnt) ? stt + ki : N + b;
        size_t so = (size_t)grow * 256 + h * 32 + shalf;
        unsigned d0 = dRow + stg_i * (A_STG * 4);
#pragma unroll
        for (int i = 0; i < 4; i++) {
            cpa16(d0 + 16 * i,              g_kh + so + 4 * i, 16);
            cpa16(d0 + 16 * i + KL_OFF * 4, g_kl + so + 4 * i, 16);
            cpa16(d0 + 16 * i + VH_OFF * 4, g_vh + so + 4 * i, 16);
            cpa16(d0 + 16 * i + VL_OFF * 4, g_vl + so + 4 * i, 16);
        }
        CP_COMMIT();
    };

    float m0 = -1e30f, m1 = -1e30f, l0 = 0.f, l1 = 0.f;
    float o[8][4];
#pragma unroll
    for (int nt = 0; nt < 8; nt++)
#pragma unroll
        for (int i = 0; i < 4; i++) o[nt][i] = 0.f;

    int vkey = ((lane >> 3) & 1) * 8 + (lane & 7);
    int vdof = (lane >> 4) * 4;

    int nch = (Lb + 63) >> 6;
    issue(0, 0);
    for (int kt = 0; kt < nch; kt++) {
        if (kt + 1 < nch) { issue((kt + 1) & 1, kt + 1); CP_WAIT1(); }
        else              { CP_WAIT0(); }
        __syncthreads();
        int sb = (kt & 1) * A_STG;

        // S = Q K^T (3-term fp16)
        float s[8][4];
#pragma unroll
        for (int nt = 0; nt < 8; nt++) {
            s[nt][0] = s[nt][1] = s[nt][2] = s[nt][3] = 0.f;
#pragma unroll
            for (int ks = 0; ks < 4; ks++) {
                int ko = sb + (nt * 8 + lr) * AST + ks * 8 + lc;
                unsigned bh[2] = {sm[ko], sm[ko + 4]};
                unsigned bl[2] = {sm[ko + KL_OFF], sm[ko + KL_OFF + 4]};
                mma16(s[nt], qh[ks],  bh);
                mma16(s[nt], qlo[ks], bh);
                mma16(s[nt], qh[ks],  bl);
            }
        }
        int cb = kt * 64 + 2 * lc;
#pragma unroll
        for (int nt = 0; nt < 8; nt++) {
            int c0 = cb + nt * 8, c1 = c0 + 1;
            bool v0 = c0 < Lb, v1 = c1 < Lb;
            s[nt][0] = v0 ? s[nt][0] * 0.125f : -1e30f;
            s[nt][1] = v1 ? s[nt][1] * 0.125f : -1e30f;
            s[nt][2] = v0 ? s[nt][2] * 0.125f : -1e30f;
            s[nt][3] = v1 ? s[nt][3] * 0.125f : -1e30f;
        }
        float cm0 = -1e30f, cm1 = -1e30f;
#pragma unroll
        for (int nt = 0; nt < 8; nt++) {
            cm0 = fmaxf(cm0, fmaxf(s[nt][0], s[nt][1]));
            cm1 = fmaxf(cm1, fmaxf(s[nt][2], s[nt][3]));
        }
        cm0 = fmaxf(cm0, __shfl_xor_sync(0xffffffffu, cm0, 1));
        cm0 = fmaxf(cm0, __shfl_xor_sync(0xffffffffu, cm0, 2));
        cm1 = fmaxf(cm1, __shfl_xor_sync(0xffffffffu, cm1, 1));
        cm1 = fmaxf(cm1, __shfl_xor_sync(0xffffffffu, cm1, 2));
        float mn0 = fmaxf(m0, cm0), mn1 = fmaxf(m1, cm1);
        float corr0 = __expf(m0 - mn0), corr1 = __expf(m1 - mn1);
        m0 = mn0; m1 = mn1;

        float sum0 = 0.f, sum1 = 0.f;
        unsigned pah[4][4], pal[4][4];
#pragma unroll
        for (int nt = 0; nt < 8; nt++) {
            float p0 = __expf(s[nt][0] - m0), p1 = __expf(s[nt][1] - m0);
            float p2 = __expf(s[nt][2] - m1), p3 = __expf(s[nt][3] - m1);
            sum0 += p0 + p1; sum1 += p2 + p3;
            unsigned h01, l01, h23, l23;
            splitpair(p0, p1, h01, l01);
            splitpair(p2, p3, h23, l23);
            int kq = nt >> 1, sl = (nt & 1) * 2;
            pah[kq][sl] = h01; pah[kq][sl + 1] = h23;
            pal[kq][sl] = l01; pal[kq][sl + 1] = l23;
        }
        sum0 += __shfl_xor_sync(0xffffffffu, sum0, 1);
        sum0 += __shfl_xor_sync(0xffffffffu, sum0, 2);
        sum1 += __shfl_xor_sync(0xffffffffu, sum1, 1);
        sum1 += __shfl_xor_sync(0xffffffffu, sum1, 2);
        l0 = l0 * corr0 + sum0;
        l1 = l1 * corr1 + sum1;
#pragma unroll
        for (int nt = 0; nt < 8; nt++) {
            o[nt][0] *= corr0; o[nt][1] *= corr0;
            o[nt][2] *= corr1; o[nt][3] *= corr1;
        }
        // O += P V (3-term) via ldmatrix.x4.trans
#pragma unroll
        for (int kq = 0; kq < 4; kq++) {
#pragma unroll
            for (int ntp = 0; ntp < 4; ntp++) {
                unsigned va = smb + 4 * (sb + VH_OFF + (kq * 16 + vkey) * AST + ntp * 8 + vdof);
                unsigned dh_[4], dl_[4];
                ldm4t(dh_, va);
                ldm4t(dl_, va + (VL_OFF - VH_OFF) * 4);
                unsigned bh01[2] = {dh_[0], dh_[1]}, bh23[2] = {dh_[2], dh_[3]};
                unsigned bl01[2] = {dl_[0], dl_[1]}, bl23[2] = {dl_[2], dl_[3]};
                mma16(o[2*ntp],     pah[kq], bh01);
                mma16(o[2*ntp],     pal[kq], bh01);
                mma16(o[2*ntp],     pah[kq], bl01);
                mma16(o[2*ntp + 1], pah[kq], bh23);
                mma16(o[2*ntp + 1], pal[kq], bh23);
                mma16(o[2*ntp + 1], pah[kq], bl23);
            }
        }
        __syncthreads();
    }

    float inv0 = 1.f / l0, inv1 = 1.f / l1;
    int q0 = qt * 64 + warp * 16 + lr;
    int q1 = q0 + 8;
    if (q0 < Lb) {
        int gr = (q0 < cnt) ? stt + q0 : N + b;
        size_t p = (size_t)gr * 256 + h * 32 + lc;
#pragma unroll
        for (int nt = 0; nt < 8; nt++) {
            unsigned hh, ll;
            splitpair(o[nt][0] * inv0, o[nt][1] * inv0, hh, ll);
            g_ath[p + nt * 4] = hh; g_atl[p + nt * 4] = ll;
        }
    }
    if (q1 < Lb) {
        int gr = (q1 < cnt) ? stt + q1 : N + b;
        size_t p = (size_t)gr * 256 + h * 32 + lc;
#pragma unroll
        for (int nt = 0; nt < 8; nt++) {
            unsigned hh, ll;
            splitpair(o[nt][2] * inv1, o[nt][3] * inv1, hh, ll);
            g_ath[p + nt * 4] = hh; g_atl[p + nt * 4] = ll;
        }
    }
}

// ---------------- LayerNorm ----------------
template<bool PLANES>
__device__ __forceinline__ void row_ln(const float* __restrict__ src,
                                       const float* __restrict__ gam,
                                       const float* __restrict__ bet,
                                       float* __restrict__ dst,
                                       unsigned* __restrict__ ph,
                                       unsigned* __restrict__ pl,
                                       int row) {
    int tid = threadIdx.x;
    float4 v = ((const float4*)src)[tid];
    float s  = v.x + v.y + v.z + v.w;
    float ss = v.x*v.x + v.y*v.y + v.z*v.z + v.w*v.w;
#pragma unroll
    for (int off = 16; off; off >>= 1) {
        s  += __shfl_xor_sync(0xffffffffu, s,  off);
        ss += __shfl_xor_sync(0xffffffffu, ss, off);
    }
    __shared__ float sh[4][2];
    int w = tid >> 5;
    if ((tid & 31) == 0) { sh[w][0] = s; sh[w][1] = ss; }
    __syncthreads();
    s  = sh[0][0] + sh[1][0] + sh[2][0] + sh[3][0];
    ss = sh[0][1] + sh[1][1] + sh[2][1] + sh[3][1];
    float mean = s * (1.f / 512.f);
    float var  = ss * (1.f / 512.f) - mean * mean;
    float rr = rsqrtf(var + 1e-5f);
    float4 gg = ((const float4*)gam)[tid];
    float4 bb = ((const float4*)bet)[tid];
    float4 out;
    out.x = (v.x - mean) * rr * gg.x + bb.x;
    out.y = (v.y - mean) * rr * gg.y + bb.y;
    out.z = (v.z - mean) * rr * gg.z + bb.z;
    out.w = (v.w - mean) * rr * gg.w + bb.w;
    ((float4*)dst)[tid] = out;
    if (PLANES) {
        unsigned h0, l0, h1, l1;
        splitpair(out.x, out.y, h0, l0);
        splitpair(out.z, out.w, h1, l1);
        size_t p = (size_t)row * 256 + 2 * tid;
        ph[p] = h0; ph[p + 1] = h1;
        pl[p] = l0; pl[p + 1] = l1;
    }
}

__global__ void k_ln0(const float* __restrict__ gam, const float* __restrict__ bet) {
    int row = blockIdx.x;
    row_ln<true>(g_ao + (size_t)row * D512, gam, bet,
                 g_hn + (size_t)row * D512, g_hnh, g_hnl, row);
}
__global__ void k_ln1(const float* __restrict__ gam, const float* __restrict__ bet,
                      float* __restrict__ out) {
    int row = blockIdx.x;
    row_ln<false>(g_f + (size_t)row * D512, gam, bet,
                  out + (size_t)row * D512, (unsigned*)0, (unsigned*)0, row);
}

// ---------------- launch ----------------
extern "C" void kernel_launch(void* const* d_in, const int* in_sizes, int n_in,
                              void* d_out, int out_size) {
    const float* x     = (const float*)d_in[0];
    const int*   batch = (const int*)  d_in[1];
    const float* cls   = (const float*)d_in[2];
    const float* Wq = (const float*)d_in[3];  const float* bq = (const float*)d_in[4];
    const float* Wk = (const float*)d_in[5];  const float* bk = (const float*)d_in[6];
    const float* Wv = (const float*)d_in[7];  const float* bv = (const float*)d_in[8];
    const float* Wo = (const float*)d_in[9];  const float* bo = (const float*)d_in[10];
    const float* W1 = (const float*)d_in[11]; const float* b1 = (const float*)d_in[12];
    const float* W2 = (const float*)d_in[13]; const float* b2 = (const float*)d_in[14];
    const float* g0 = (const float*)d_in[15]; const float* be0 = (const float*)d_in[16];
    const float* ga1 = (const float*)d_in[17]; const float* be1 = (const float*)d_in[18];

    int N = in_sizes[0] / D512;      // 16384
    int B = in_sizes[2] / D512;      // 32
    int M2 = N + B;                  // 16416

    cudaFuncSetAttribute(k_qkv,  cudaFuncAttributeMaxDynamicSharedMemorySize, GEMM_SMEM_BYTES);
    cudaFuncSetAttribute(k_wo,   cudaFuncAttributeMaxDynamicSharedMemorySize, GEMM_SMEM_BYTES);
    cudaFuncSetAttribute(k_ffn1, cudaFuncAttributeMaxDynamicSharedMemorySize, GEMM_SMEM_BYTES);
    cudaFuncSetAttribute(k_ffn2, cudaFuncAttributeMaxDynamicSharedMemorySize, GEMM_SMEM_BYTES);
    cudaFuncSetAttribute(k_attn_mma, cudaFuncAttributeMaxDynamicSharedMemorySize, ATT_SMEM);

    k_starts<<<1, 64>>>(batch, N, B);
    k_splitW<<<WTOT / 256, 256>>>(Wq, Wk, Wv, Wo, W1, W2);
    k_xc<<<M2, 128>>>(x, cls, N);

    int my = (M2 + 127) / 128;       // 129
    k_qkv<<<dim3(4, my, 3), 256, GEMM_SMEM_BYTES>>>(bq, bk, bv, M2);

    k_attn_mma<<<dim3(13, NH, B), 128, ATT_SMEM>>>(N);

    k_wo<<<dim3(4, my), 256, GEMM_SMEM_BYTES>>>(bo, M2);

    k_ln0<<<M2, 128>>>(g0, be0);

    k_ffn1<<<dim3(8, my), 256, GEMM_SMEM_BYTES>>>(b1, M2);
    k_ffn2<<<dim3(4, my), 256, GEMM_SMEM_BYTES>>>(b2, M2);

    k_ln1<<<M2, 128>>>(ga1, be1, (float*)d_out);
}

// round 16
// speedup vs baseline: 1.0176x; 1.0176x over previous
#include <cuda_runtime.h>
#include <cuda_fp16.h>
#include <math.h>

// ---------------- problem constants ----------------
#define D512 512
#define NH   8
#define DH   64
#define BMAX 32
#define NMAX 16384
#define MROWS (NMAX + BMAX)   // 16416

// ---------------- fp32 scratch ----------------
__device__ __align__(256) float g_xc[MROWS * D512];
__device__ __align__(256) float g_ao[MROWS * D512];
__device__ __align__(256) float g_hn[MROWS * D512];
__device__ __align__(256) float g_f [MROWS * D512];
__device__ int g_starts[BMAX + 1];

// ---------------- fp16 split planes (u32 = 2 fp16, low half = even k) ----------------
__device__ __align__(256) unsigned g_xch[MROWS * 256], g_xcl[MROWS * 256];
__device__ __align__(256) unsigned g_qh [MROWS * 256], g_ql [MROWS * 256];
__device__ __align__(256) unsigned g_kh [MROWS * 256], g_kl [MROWS * 256];
__device__ __align__(256) unsigned g_vh [MROWS * 256], g_vl [MROWS * 256];
__device__ __align__(256) unsigned g_ath[MROWS * 256], g_atl[MROWS * 256];
__device__ __align__(256) unsigned g_hnh[MROWS * 256], g_hnl[MROWS * 256];
__device__ __align__(256) unsigned g_th [MROWS * 512], g_tl [MROWS * 512];
// weight hi planes only (2-term GEMM), pre-paired along k: u32[k2*N+n] = {W[2k2][n], W[2k2+1][n]}
#define WQ_OFF 0
#define WK_OFF 131072
#define WV_OFF 262144
#define WO_OFF 393216
#define W1_OFF 524288
#define W2_OFF 786432
#define WTOT   1048576
__device__ __align__(256) unsigned g_wh[WTOT];

// ---------------- helpers ----------------
__device__ __forceinline__ void splitpair(float x, float y, unsigned& h, unsigned& l) {
    __half hx = __float2half_rn(x);
    __half hy = __float2half_rn(y);
    __half lx = __float2half_rn(x - __half2float(hx));
    __half ly = __float2half_rn(y - __half2float(hy));
    __half2 hh = __halves2half2(hx, hy);
    __half2 ll = __halves2half2(lx, ly);
    h = *(unsigned*)&hh; l = *(unsigned*)&ll;
}
__device__ __forceinline__ unsigned hipair(float x, float y) {
    __half2 hh = __halves2half2(__float2half_rn(x), __float2half_rn(y));
    return *(unsigned*)&hh;
}
__device__ __forceinline__ void mma16(float* c, const unsigned* a, const unsigned* b) {
    asm volatile(
        "mma.sync.aligned.m16n8k16.row.col.f32.f16.f16.f32 "
        "{%0,%1,%2,%3}, {%4,%5,%6,%7}, {%8,%9}, {%0,%1,%2,%3};"
        : "+f"(c[0]), "+f"(c[1]), "+f"(c[2]), "+f"(c[3])
        : "r"(a[0]), "r"(a[1]), "r"(a[2]), "r"(a[3]), "r"(b[0]), "r"(b[1]));
}
__device__ __forceinline__ void ldm4(unsigned* d, unsigned a) {
    asm volatile("ldmatrix.sync.aligned.m8n8.x4.shared.b16 {%0,%1,%2,%3}, [%4];"
        : "=r"(d[0]), "=r"(d[1]), "=r"(d[2]), "=r"(d[3]) : "r"(a));
}
__device__ __forceinline__ void ldm4t(unsigned* d, unsigned a) {
    asm volatile("ldmatrix.sync.aligned.m8n8.x4.trans.shared.b16 {%0,%1,%2,%3}, [%4];"
        : "=r"(d[0]), "=r"(d[1]), "=r"(d[2]), "=r"(d[3]) : "r"(a));
}
__device__ __forceinline__ void cpa16(unsigned dst, const void* src, int sz) {
    asm volatile("cp.async.cg.shared.global [%0], [%1], 16, %2;"
        :: "r"(dst), "l"(src), "r"(sz));
}
#define CP_COMMIT() asm volatile("cp.async.commit_group;")
#define CP_WAIT0()  asm volatile("cp.async.wait_group 0;")
#define CP_WAIT1()  asm volatile("cp.async.wait_group 1;")
#define CP_WAIT2()  asm volatile("cp.async.wait_group 2;")

// ---------------- starts ----------------
__global__ void k_starts(const int* __restrict__ batch, int N, int B) {
    int b = threadIdx.x;
    if (b > B) return;
    int lo = 0, hi = N;
    while (lo < hi) {
        int mid = (lo + hi) >> 1;
        if (batch[mid] < b) lo = mid + 1; else hi = mid;
    }
    g_starts[b] = lo;
}

// ---------------- weight split (hi plane only, pre-paired along k) ----------------
__global__ void k_splitW(const float* __restrict__ Wq, const float* __restrict__ Wk,
                         const float* __restrict__ Wv, const float* __restrict__ Wo,
                         const float* __restrict__ W1, const float* __restrict__ W2) {
    int t = blockIdx.x * 256 + threadIdx.x;
    if (t >= WTOT) return;
    const float* W; int rel; bool n1024 = false;
    if      (t < WK_OFF) { W = Wq; rel = t; }
    else if (t < WV_OFF) { W = Wk; rel = t - WK_OFF; }
    else if (t < WO_OFF) { W = Wv; rel = t - WV_OFF; }
    else if (t < W1_OFF) { W = Wo; rel = t - WO_OFF; }
    else if (t < W2_OFF) { W = W1; rel = t - W1_OFF; n1024 = true; }
    else                 { W = W2; rel = t - W2_OFF; }
    int N = n1024 ? 1024 : 512;
    int k2 = n1024 ? (rel >> 10) : (rel >> 9);
    int n  = rel & (N - 1);
    g_wh[t] = hipair(W[(size_t)(2 * k2) * N + n], W[(size_t)(2 * k2 + 1) * N + n]);
}

// ---------------- compact input [x; CLS] -> fp32 + planes ----------------
__global__ void k_xc(const float* __restrict__ x, const float* __restrict__ cls, int N) {
    int row = blockIdx.x;
    int tid = threadIdx.x;
    const float* src = (row < N) ? (x + (size_t)row * D512)
                                 : (cls + (size_t)(row - N) * D512);
    float4 v = ((const float4*)src)[tid];
    ((float4*)(g_xc + (size_t)row * D512))[tid] = v;
    unsigned h0, l0, h1, l1;
    splitpair(v.x, v.y, h0, l0);
    splitpair(v.z, v.w, h1, l1);
    size_t p = (size_t)row * 256 + 2 * tid;
    g_xch[p] = h0; g_xch[p + 1] = h1;
    g_xcl[p] = l0; g_xcl[p + 1] = l1;
}

// ---------------- pipelined 2-term fp16 GEMM (3-stage cp.async) ----------------
// A planes hi+lo [M][K/2] u32, B hi plane pre-paired [K/2][N] u32.
// C = (Ah+Al)·Bh + bias [+res] [relu]; 128x128 tile, K-chunk 32, 3-stage pipeline.
#define STGU 7296                 // A 2*2560 + B 2176
#define A_LO 2560
#define B_HI 5120
#define GEMM_SMEM_BYTES (3 * STGU * 4)   // 87552

template<bool RELU, bool HASRES, bool WF32, bool WPL>
__device__ __forceinline__ void gemm_core(
    const unsigned* __restrict__ Ah, const unsigned* __restrict__ Al,
    const unsigned* __restrict__ Bh,
    const float* __restrict__ bias, const float* __restrict__ res,
    float* __restrict__ C, unsigned* __restrict__ CPh, unsigned* __restrict__ CPl,
    int M, int N, int K)
{
    extern __shared__ unsigned sm[];
    const int Ku = K >> 1;
    int tid = threadIdx.x, lane = tid & 31, warp = tid >> 5;
    int wm = warp >> 2, wn = warp & 3;
    int brow = blockIdx.y * 128, bcol = blockIdx.x * 128;
    unsigned smb = (unsigned)__cvta_generic_to_shared(sm);

    float acc[4][4][4];
#pragma unroll
    for (int mt = 0; mt < 4; mt++)
#pragma unroll
        for (int nt = 0; nt < 4; nt++)
#pragma unroll
            for (int i = 0; i < 4; i++) acc[mt][nt][i] = 0.f;

    int arow = tid >> 2, aq = tid & 3;
    int bk2  = tid >> 5, bq = tid & 31;
    int ag0 = brow + arow, ag1 = ag0 + 64;
    int as0 = (ag0 < M) ? 16 : 0, as1 = (ag1 < M) ? 16 : 0;
    const unsigned* Ar0h = Ah + (size_t)((ag0 < M) ? ag0 : 0) * Ku + aq * 4;
    const unsigned* Ar1h = Ah + (size_t)((ag1 < M) ? ag1 : 0) * Ku + aq * 4;
    const unsigned* Ar0l = Al + (size_t)((ag0 < M) ? ag0 : 0) * Ku + aq * 4;
    const unsigned* Ar1l = Al + (size_t)((ag1 < M) ? ag1 : 0) * Ku + aq * 4;
    const unsigned* B0h = Bh + (size_t)bk2 * N + bcol + bq * 4;
    const unsigned* B1h = Bh + (size_t)(bk2 + 8) * N + bcol + bq * 4;
    unsigned dA0 = smb + 4 * (arow * 20 + aq * 4);
    unsigned dA1 = smb + 4 * ((arow + 64) * 20 + aq * 4);
    unsigned dB0 = smb + 4 * (B_HI + bk2 * 136 + bq * 4);
    unsigned dB1 = smb + 4 * (B_HI + (bk2 + 8) * 136 + bq * 4);

    int nch = K >> 5;

    auto issue = [&](int st, int ch) {
        unsigned so = st * (STGU * 4);
        int ko = ch * 16;
        cpa16(so + dA0,            Ar0h + ko, as0);
        cpa16(so + dA1,            Ar1h + ko, as1);
        cpa16(so + dA0 + A_LO * 4, Ar0l + ko, as0);
        cpa16(so + dA1 + A_LO * 4, Ar1l + ko, as1);
        size_t bko = (size_t)ko * N;
        cpa16(so + dB0, B0h + bko, 16);
        cpa16(so + dB1, B1h + bko, 16);
        CP_COMMIT();
    };

    issue(0, 0);
    if (nch > 1) issue(1, 1);

    int r = lane >> 2, cl = lane & 3;
    int lrow = lane & 15, kq = lane >> 4;
    for (int ch = 0; ch < nch; ch++) {
        if (ch + 2 < nch) issue((ch + 2) % 3, ch + 2);
        int ahead = nch - 1 - ch; if (ahead > 2) ahead = 2;
        if (ahead == 2) { CP_WAIT2(); }
        else if (ahead == 1) { CP_WAIT1(); }
        else { CP_WAIT0(); }
        __syncthreads();
        int base = (ch % 3) * STGU;
#pragma unroll
        for (int s = 0; s < 2; s++) {
            unsigned ah[4][4], al[4][4];
#pragma unroll
            for (int mt = 0; mt < 4; mt++) {
                unsigned ao_ = smb + 4 * (base + (wm * 64 + mt * 16 + lrow) * 20 + s * 8 + kq * 4);
                ldm4(ah[mt], ao_);
                ldm4(al[mt], ao_ + A_LO * 4);
            }
            unsigned bhf[4][2];
#pragma unroll
            for (int nt = 0; nt < 4; nt++) {
                int o = base + B_HI + (s * 8 + cl) * 136 + wn * 32 + nt * 8 + r;
                bhf[nt][0] = sm[o];  bhf[nt][1] = sm[o + 4 * 136];
            }
#pragma unroll
            for (int mt = 0; mt < 4; mt++)
#pragma unroll
                for (int nt = 0; nt < 4; nt++) {
                    mma16(acc[mt][nt], ah[mt], bhf[nt]);
                    mma16(acc[mt][nt], al[mt], bhf[nt]);
                }
        }
        __syncthreads();
    }

#pragma unroll
    for (int mt = 0; mt < 4; mt++) {
        int row0 = brow + wm * 64 + mt * 16 + r;
        int row1 = row0 + 8;
#pragma unroll
        for (int nt = 0; nt < 4; nt++) {
            int col = bcol + wn * 32 + nt * 8 + cl * 2;
            float2 bb = *(const float2*)(bias + col);
            const float* c = acc[mt][nt];
#pragma unroll
            for (int half = 0; half < 2; half++) {
                int row = half ? row1 : row0;
                if (row < M) {
                    float v0 = c[2 * half] + bb.x, v1 = c[2 * half + 1] + bb.y;
                    if (HASRES) {
                        float2 rv = *(const float2*)(res + (size_t)row * N + col);
                        v0 += rv.x; v1 += rv.y;
                    }
                    if (RELU) { v0 = fmaxf(v0, 0.f); v1 = fmaxf(v1, 0.f); }
                    if (WF32)
                        *(float2*)(C + (size_t)row * N + col) = make_float2(v0, v1);
                    if (WPL) {
                        unsigned h, l;
                        splitpair(v0, v1, h, l);
                        size_t p = ((size_t)row * N + col) >> 1;
                        CPh[p] = h; CPl[p] = l;
                    }
                }
            }
        }
    }
}

__global__ void __launch_bounds__(256, 2) k_qkv(
    const float* __restrict__ bq, const float* __restrict__ bk,
    const float* __restrict__ bv, int M)
{
    const unsigned* Bh; const float* bias; unsigned* Ph; unsigned* Pl;
    if (blockIdx.z == 0)      { Bh = g_wh + WQ_OFF; bias = bq; Ph = g_qh; Pl = g_ql; }
    else if (blockIdx.z == 1) { Bh = g_wh + WK_OFF; bias = bk; Ph = g_kh; Pl = g_kl; }
    else                      { Bh = g_wh + WV_OFF; bias = bv; Ph = g_vh; Pl = g_vl; }
    gemm_core<false, false, false, true>(g_xch, g_xcl, Bh, bias,
        (const float*)0, (float*)0, Ph, Pl, M, 512, 512);
}
__global__ void __launch_bounds__(256, 2) k_wo(const float* __restrict__ bo, int M) {
    gemm_core<false, true, true, false>(g_ath, g_atl, g_wh + WO_OFF,
        bo, g_xc, g_ao, (unsigned*)0, (unsigned*)0, M, 512, 512);
}
__global__ void __launch_bounds__(256, 2) k_ffn1(const float* __restrict__ b1, int M) {
    gemm_core<true, false, false, true>(g_hnh, g_hnl, g_wh + W1_OFF,
        b1, (const float*)0, (float*)0, g_th, g_tl, M, 1024, 512);
}
__global__ void __launch_bounds__(256, 2) k_ffn2(const float* __restrict__ b2, int M) {
    gemm_core<false, true, true, false>(g_th, g_tl, g_wh + W2_OFF,
        b2, g_hn, g_f, (unsigned*)0, (unsigned*)0, M, 512, 1024);
}

// ---------------- fp16 flash attention: q-tile 128, 8 warps, double-buffered K/V ----------------
// stage (9216 u32): [0..2304) KsHi [2304..4608) KsLo [4608..6912) VsHi [6912..9216) VsLo
// K/V rows [0..63] x 32 u32 dim-pairs, stride 36 (conflict-free). Q staged across full stage 0.
#define AST 36
#define A_STG 9216
#define KL_OFF 2304
#define VH_OFF 4608
#define VL_OFF 6912
#define ATT_SMEM (2 * A_STG * 4)   // 73728

__global__ void __launch_bounds__(256) k_attn_mma(int N) {
    extern __shared__ unsigned sm[];
    int b = blockIdx.z, h = blockIdx.y, qt = blockIdx.x;
    int stt = g_starts[b];
    int cnt = g_starts[b + 1] - stt;
    int Lb = cnt + 1;
    if (qt * 128 >= Lb) return;
    int tid = threadIdx.x, lane = tid & 31, warp = tid >> 5;
    int lr = lane >> 2, lc = lane & 3;
    unsigned smb = (unsigned)__cvta_generic_to_shared(sm);

    // ---- stage Q (128 rows) into the FULL stage-0 region: hi at 0, lo at 4608 ----
    {
        int qrow = tid >> 1, qhalf = (tid & 1) * 16;       // 256 thr: 128 rows x 2 halves
        int qi = qt * 128 + qrow;
        int grow = (qi < cnt) ? stt + qi : N + b;
        size_t so = (size_t)grow * 256 + h * 32 + qhalf;
        unsigned dQ = smb + 4 * (qrow * AST + qhalf);
#pragma unroll
        for (int i = 0; i < 4; i++) {
            cpa16(dQ + 16 * i,                g_qh + so + 4 * i, 16);
            cpa16(dQ + 16 * i + VH_OFF * 4,   g_ql + so + 4 * i, 16);
        }
        CP_COMMIT(); CP_WAIT0();
    }
    __syncthreads();
    unsigned qh[4][4], qlo[4][4];
    {
        int rq = warp * 16 + lr;                           // warps 0..7 -> rows 0..127
#pragma unroll
        for (int ks = 0; ks < 4; ks++) {
            int c0 = ks * 8 + lc;
            qh[ks][0]  = sm[rq*AST + c0];               qh[ks][1]  = sm[(rq+8)*AST + c0];
            qh[ks][2]  = sm[rq*AST + c0 + 4];           qh[ks][3]  = sm[(rq+8)*AST + c0 + 4];
            qlo[ks][0] = sm[VH_OFF + rq*AST + c0];      qlo[ks][1] = sm[VH_OFF + (rq+8)*AST + c0];
            qlo[ks][2] = sm[VH_OFF + rq*AST + c0 + 4];  qlo[ks][3] = sm[VH_OFF + (rq+8)*AST + c0 + 4];
        }
    }
    __syncthreads();

    // K/V staging: 4 threads per key-row, 8 u32 each (2 cpa16 per plane)
    int ksrow = tid >> 2, ksq = (tid & 3) * 8;
    unsigned dKV = smb + 4 * (ksrow * AST + ksq);
    auto issue = [&](int stg_i, int kt) {
        int ki = kt * 64 + ksrow;
        int grow = (ki < cnt) ? stt + ki : N + b;
        size_t so = (size_t)grow * 256 + h * 32 + ksq;
        unsigned d0 = dKV + stg_i * (A_STG * 4);
#pragma unroll
        for (int i = 0; i < 2; i++) {
            cpa16(d0 + 16 * i,              g_kh + so + 4 * i, 16);
            cpa16(d0 + 16 * i + KL_OFF * 4, g_kl + so + 4 * i, 16);
            cpa16(d0 + 16 * i + VH_OFF * 4, g_vh + so + 4 * i, 16);
            cpa16(d0 + 16 * i + VL_OFF * 4, g_vl + so + 4 * i, 16);
        }
        CP_COMMIT();
    };

    float m0 = -1e30f, m1 = -1e30f, l0 = 0.f, l1 = 0.f;
    float o[8][4];
#pragma unroll
    for (int nt = 0; nt < 8; nt++)
#pragma unroll
        for (int i = 0; i < 4; i++) o[nt][i] = 0.f;

    int vkey = ((lane >> 3) & 1) * 8 + (lane & 7);
    int vdof = (lane >> 4) * 4;

    int nch = (Lb + 63) >> 6;
    issue(0, 0);
    for (int kt = 0; kt < nch; kt++) {
        if (kt + 1 < nch) { issue((kt + 1) & 1, kt + 1); CP_WAIT1(); }
        else              { CP_WAIT0(); }
        __syncthreads();
        int sb = (kt & 1) * A_STG;

        // S = Q K^T (3-term fp16)
        float s[8][4];
#pragma unroll
        for (int nt = 0; nt < 8; nt++) {
            s[nt][0] = s[nt][1] = s[nt][2] = s[nt][3] = 0.f;
#pragma unroll
            for (int ks = 0; ks < 4; ks++) {
                int ko = sb + (nt * 8 + lr) * AST + ks * 8 + lc;
                unsigned bh[2] = {sm[ko], sm[ko + 4]};
                unsigned bl[2] = {sm[ko + KL_OFF], sm[ko + KL_OFF + 4]};
                mma16(s[nt], qh[ks],  bh);
                mma16(s[nt], qlo[ks], bh);
                mma16(s[nt], qh[ks],  bl);
            }
        }
        int cb = kt * 64 + 2 * lc;
#pragma unroll
        for (int nt = 0; nt < 8; nt++) {
            int c0 = cb + nt * 8, c1 = c0 + 1;
            bool v0 = c0 < Lb, v1 = c1 < Lb;
            s[nt][0] = v0 ? s[nt][0] * 0.125f : -1e30f;
            s[nt][1] = v1 ? s[nt][1] * 0.125f : -1e30f;
            s[nt][2] = v0 ? s[nt][2] * 0.125f : -1e30f;
            s[nt][3] = v1 ? s[nt][3] * 0.125f : -1e30f;
        }
        float cm0 = -1e30f, cm1 = -1e30f;
#pragma unroll
        for (int nt = 0; nt < 8; nt++) {
            cm0 = fmaxf(cm0, fmaxf(s[nt][0], s[nt][1]));
            cm1 = fmaxf(cm1, fmaxf(s[nt][2], s[nt][3]));
        }
        cm0 = fmaxf(cm0, __shfl_xor_sync(0xffffffffu, cm0, 1));
        cm0 = fmaxf(cm0, __shfl_xor_sync(0xffffffffu, cm0, 2));
        cm1 = fmaxf(cm1, __shfl_xor_sync(0xffffffffu, cm1, 1));
        cm1 = fmaxf(cm1, __shfl_xor_sync(0xffffffffu, cm1, 2));
        float mn0 = fmaxf(m0, cm0), mn1 = fmaxf(m1, cm1);
        float corr0 = __expf(m0 - mn0), corr1 = __expf(m1 - mn1);
        m0 = mn0; m1 = mn1;

        float sum0 = 0.f, sum1 = 0.f;
        unsigned pah[4][4], pal[4][4];
#pragma unroll
        for (int nt = 0; nt < 8; nt++) {
            float p0 = __expf(s[nt][0] - m0), p1 = __expf(s[nt][1] - m0);
            float p2 = __expf(s[nt][2] - m1), p3 = __expf(s[nt][3] - m1);
            sum0 += p0 + p1; sum1 += p2 + p3;
            unsigned h01, l01, h23, l23;
            splitpair(p0, p1, h01, l01);
            splitpair(p2, p3, h23, l23);
            int kq = nt >> 1, sl = (nt & 1) * 2;
            pah[kq][sl] = h01; pah[kq][sl + 1] = h23;
            pal[kq][sl] = l01; pal[kq][sl + 1] = l23;
        }
        sum0 += __shfl_xor_sync(0xffffffffu, sum0, 1);
        sum0 += __shfl_xor_sync(0xffffffffu, sum0, 2);
        sum1 += __shfl_xor_sync(0xffffffffu, sum1, 1);
        sum1 += __shfl_xor_sync(0xffffffffu, sum1, 2);
        l0 = l0 * corr0 + sum0;
        l1 = l1 * corr1 + sum1;
#pragma unroll
        for (int nt = 0; nt < 8; nt++) {
            o[nt][0] *= corr0; o[nt][1] *= corr0;
            o[nt][2] *= corr1; o[nt][3] *= corr1;
        }
        // O += P V (3-term) via ldmatrix.x4.trans
#pragma unroll
        for (int kq = 0; kq < 4; kq++) {
#pragma unroll
            for (int ntp = 0; ntp < 4; ntp++) {
                unsigned va = smb + 4 * (sb + VH_OFF + (kq * 16 + vkey) * AST + ntp * 8 + vdof);
                unsigned dh_[4], dl_[4];
                ldm4t(dh_, va);
                ldm4t(dl_, va + (VL_OFF - VH_OFF) * 4);
                unsigned bh01[2] = {dh_[0], dh_[1]}, bh23[2] = {dh_[2], dh_[3]};
                unsigned bl01[2] = {dl_[0], dl_[1]}, bl23[2] = {dl_[2], dl_[3]};
                mma16(o[2*ntp],     pah[kq], bh01);
                mma16(o[2*ntp],     pal[kq], bh01);
                mma16(o[2*ntp],     pah[kq], bl01);
                mma16(o[2*ntp + 1], pah[kq], bh23);
                mma16(o[2*ntp + 1], pal[kq], bh23);
                mma16(o[2*ntp + 1], pah[kq], bl23);
            }
        }
        __syncthreads();
    }

    float inv0 = 1.f / l0, inv1 = 1.f / l1;
    int q0 = qt * 128 + warp * 16 + lr;
    int q1 = q0 + 8;
    if (q0 < Lb) {
        int gr = (q0 < cnt) ? stt + q0 : N + b;
        size_t p = (size_t)gr * 256 + h * 32 + lc;
#pragma unroll
        for (int nt = 0; nt < 8; nt++) {
            unsigned hh, ll;
            splitpair(o[nt][0] * inv0, o[nt][1] * inv0, hh, ll);
            g_ath[p + nt * 4] = hh; g_atl[p + nt * 4] = ll;
        }
    }
    if (q1 < Lb) {
        int gr = (q1 < cnt) ? stt + q1 : N + b;
        size_t p = (size_t)gr * 256 + h * 32 + lc;
#pragma unroll
        for (int nt = 0; nt < 8; nt++) {
            unsigned hh, ll;
            splitpair(o[nt][2] * inv1, o[nt][3] * inv1, hh, ll);
            g_ath[p + nt * 4] = hh; g_atl[p + nt * 4] = ll;
        }
    }
}

// ---------------- LayerNorm ----------------
template<bool PLANES>
__device__ __forceinline__ void row_ln(const float* __restrict__ src,
                                       const float* __restrict__ gam,
                                       const float* __restrict__ bet,
                                       float* __restrict__ dst,
                                       unsigned* __restrict__ ph,
                                       unsigned* __restrict__ pl,
                                       int row) {
    int tid = threadIdx.x;
    float4 v = ((const float4*)src)[tid];
    float s  = v.x + v.y + v.z + v.w;
    float ss = v.x*v.x + v.y*v.y + v.z*v.z + v.w*v.w;
#pragma unroll
    for (int off = 16; off; off >>= 1) {
        s  += __shfl_xor_sync(0xffffffffu, s,  off);
        ss += __shfl_xor_sync(0xffffffffu, ss, off);
    }
    __shared__ float sh[4][2];
    int w = tid >> 5;
    if ((tid & 31) == 0) { sh[w][0] = s; sh[w][1] = ss; }
    __syncthreads();
    s  = sh[0][0] + sh[1][0] + sh[2][0] + sh[3][0];
    ss = sh[0][1] + sh[1][1] + sh[2][1] + sh[3][1];
    float mean = s * (1.f / 512.f);
    float var  = ss * (1.f / 512.f) - mean * mean;
    float rr = rsqrtf(var + 1e-5f);
    float4 gg = ((const float4*)gam)[tid];
    float4 bb = ((const float4*)bet)[tid];
    float4 out;
    out.x = (v.x - mean) * rr * gg.x + bb.x;
    out.y = (v.y - mean) * rr * gg.y + bb.y;
    out.z = (v.z - mean) * rr * gg.z + bb.z;
    out.w = (v.w - mean) * rr * gg.w + bb.w;
    ((float4*)dst)[tid] = out;
    if (PLANES) {
        unsigned h0, l0, h1, l1;
        splitpair(out.x, out.y, h0, l0);
        splitpair(out.z, out.w, h1, l1);
        size_t p = (size_t)row * 256 + 2 * tid;
        ph[p] = h0; ph[p + 1] = h1;
        pl[p] = l0; pl[p + 1] = l1;
    }
}

__global__ void k_ln0(const float* __restrict__ gam, const float* __restrict__ bet) {
    int row = blockIdx.x;
    row_ln<true>(g_ao + (size_t)row * D512, gam, bet,
                 g_hn + (size_t)row * D512, g_hnh, g_hnl, row);
}
__global__ void k_ln1(const float* __restrict__ gam, const float* __restrict__ bet,
                      float* __restrict__ out) {
    int row = blockIdx.x;
    row_ln<false>(g_f + (size_t)row * D512, gam, bet,
                  out + (size_t)row * D512, (unsigned*)0, (unsigned*)0, row);
}

// ---------------- launch ----------------
extern "C" void kernel_launch(void* const* d_in, const int* in_sizes, int n_in,
                              void* d_out, int out_size) {
    const float* x     = (const float*)d_in[0];
    const int*   batch = (const int*)  d_in[1];
    const float* cls   = (const float*)d_in[2];
    const float* Wq = (const float*)d_in[3];  const float* bq = (const float*)d_in[4];
    const float* Wk = (const float*)d_in[5];  const float* bk = (const float*)d_in[6];
    const float* Wv = (const float*)d_in[7];  const float* bv = (const float*)d_in[8];
    const float* Wo = (const float*)d_in[9];  const float* bo = (const float*)d_in[10];
    const float* W1 = (const float*)d_in[11]; const float* b1 = (const float*)d_in[12];
    const float* W2 = (const float*)d_in[13]; const float* b2 = (const float*)d_in[14];
    const float* g0 = (const float*)d_in[15]; const float* be0 = (const float*)d_in[16];
    const float* ga1 = (const float*)d_in[17]; const float* be1 = (const float*)d_in[18];

    int N = in_sizes[0] / D512;      // 16384
    int B = in_sizes[2] / D512;      // 32
    int M2 = N + B;                  // 16416

    cudaFuncSetAttribute(k_qkv,  cudaFuncAttributeMaxDynamicSharedMemorySize, GEMM_SMEM_BYTES);
    cudaFuncSetAttribute(k_wo,   cudaFuncAttributeMaxDynamicSharedMemorySize, GEMM_SMEM_BYTES);
    cudaFuncSetAttribute(k_ffn1, cudaFuncAttributeMaxDynamicSharedMemorySize, GEMM_SMEM_BYTES);
    cudaFuncSetAttribute(k_ffn2, cudaFuncAttributeMaxDynamicSharedMemorySize, GEMM_SMEM_BYTES);
    cudaFuncSetAttribute(k_attn_mma, cudaFuncAttributeMaxDynamicSharedMemorySize, ATT_SMEM);

    k_starts<<<1, 64>>>(batch, N, B);
    k_splitW<<<WTOT / 256, 256>>>(Wq, Wk, Wv, Wo, W1, W2);
    k_xc<<<M2, 128>>>(x, cls, N);

    int my = (M2 + 127) / 128;       // 129
    k_qkv<<<dim3(4, my, 3), 256, GEMM_SMEM_BYTES>>>(bq, bk, bv, M2);

    k_attn_mma<<<dim3(7, NH, B), 256, ATT_SMEM>>>(N);

    k_wo<<<dim3(4, my), 256, GEMM_SMEM_BYTES>>>(bo, M2);

    k_ln0<<<M2, 128>>>(g0, be0);

    k_ffn1<<<dim3(8, my), 256, GEMM_SMEM_BYTES>>>(b1, M2);
    k_ffn2<<<dim3(4, my), 256, GEMM_SMEM_BYTES>>>(b2, M2);

    k_ln1<<<M2, 128>>>(ga1, be1, (float*)d_out);
}

// round 17
// speedup vs baseline: 1.0522x; 1.0340x over previous
#include <cuda_runtime.h>
#include <cuda_fp16.h>
#include <math.h>

// ---------------- problem constants ----------------
#define D512 512
#define NH   8
#define DH   64
#define BMAX 32
#define NMAX 16384
#define MROWS (NMAX + BMAX)   // 16416

// ---------------- fp32 scratch ----------------
__device__ __align__(256) float g_ao[MROWS * D512];
__device__ __align__(256) float g_hn[MROWS * D512];
__device__ __align__(256) float g_f [MROWS * D512];
__device__ int g_starts[BMAX + 1];

// ---------------- fp16 split planes (u32 = 2 fp16, low half = even k) ----------------
__device__ __align__(256) unsigned g_xch[MROWS * 256], g_xcl[MROWS * 256];
__device__ __align__(256) unsigned g_qh [MROWS * 256], g_ql [MROWS * 256];
__device__ __align__(256) unsigned g_kh [MROWS * 256], g_kl [MROWS * 256];
__device__ __align__(256) unsigned g_vh [MROWS * 256], g_vl [MROWS * 256];
__device__ __align__(256) unsigned g_ath[MROWS * 256], g_atl[MROWS * 256];
__device__ __align__(256) unsigned g_hnh[MROWS * 256], g_hnl[MROWS * 256];
__device__ __align__(256) unsigned g_th [MROWS * 512], g_tl [MROWS * 512];
// weight hi planes only (2-term GEMM), pre-paired along k: u32[k2*N+n] = {W[2k2][n], W[2k2+1][n]}
#define WQ_OFF 0
#define WK_OFF 131072
#define WV_OFF 262144
#define WO_OFF 393216
#define W1_OFF 524288
#define W2_OFF 786432
#define WTOT   1048576
__device__ __align__(256) unsigned g_wh[WTOT];

// ---------------- helpers ----------------
__device__ __forceinline__ void splitpair(float x, float y, unsigned& h, unsigned& l) {
    __half hx = __float2half_rn(x);
    __half hy = __float2half_rn(y);
    __half lx = __float2half_rn(x - __half2float(hx));
    __half ly = __float2half_rn(y - __half2float(hy));
    __half2 hh = __halves2half2(hx, hy);
    __half2 ll = __halves2half2(lx, ly);
    h = *(unsigned*)&hh; l = *(unsigned*)&ll;
}
__device__ __forceinline__ unsigned hipair(float x, float y) {
    __half2 hh = __halves2half2(__float2half_rn(x), __float2half_rn(y));
    return *(unsigned*)&hh;
}
__device__ __forceinline__ void mma16(float* c, const unsigned* a, const unsigned* b) {
    asm volatile(
        "mma.sync.aligned.m16n8k16.row.col.f32.f16.f16.f32 "
        "{%0,%1,%2,%3}, {%4,%5,%6,%7}, {%8,%9}, {%0,%1,%2,%3};"
        : "+f"(c[0]), "+f"(c[1]), "+f"(c[2]), "+f"(c[3])
        : "r"(a[0]), "r"(a[1]), "r"(a[2]), "r"(a[3]), "r"(b[0]), "r"(b[1]));
}
__device__ __forceinline__ void ldm4(unsigned* d, unsigned a) {
    asm volatile("ldmatrix.sync.aligned.m8n8.x4.shared.b16 {%0,%1,%2,%3}, [%4];"
        : "=r"(d[0]), "=r"(d[1]), "=r"(d[2]), "=r"(d[3]) : "r"(a));
}
__device__ __forceinline__ void ldm4t(unsigned* d, unsigned a) {
    asm volatile("ldmatrix.sync.aligned.m8n8.x4.trans.shared.b16 {%0,%1,%2,%3}, [%4];"
        : "=r"(d[0]), "=r"(d[1]), "=r"(d[2]), "=r"(d[3]) : "r"(a));
}
__device__ __forceinline__ void cpa16(unsigned dst, const void* src, int sz) {
    asm volatile("cp.async.cg.shared.global [%0], [%1], 16, %2;"
        :: "r"(dst), "l"(src), "r"(sz));
}
#define CP_COMMIT() asm volatile("cp.async.commit_group;")
#define CP_WAIT0()  asm volatile("cp.async.wait_group 0;")

// ---------------- starts ----------------
__global__ void k_starts(const int* __restrict__ batch, int N, int B) {
    int b = threadIdx.x;
    if (b > B) return;
    int lo = 0, hi = N;
    while (lo < hi) {
        int mid = (lo + hi) >> 1;
        if (batch[mid] < b) lo = mid + 1; else hi = mid;
    }
    g_starts[b] = lo;
}

// ---------------- weight split (hi plane only, pre-paired along k) ----------------
__global__ void k_splitW(const float* __restrict__ Wq, const float* __restrict__ Wk,
                         const float* __restrict__ Wv, const float* __restrict__ Wo,
                         const float* __restrict__ W1, const float* __restrict__ W2) {
    int t = blockIdx.x * 256 + threadIdx.x;
    if (t >= WTOT) return;
    const float* W; int rel; bool n1024 = false;
    if      (t < WK_OFF) { W = Wq; rel = t; }
    else if (t < WV_OFF) { W = Wk; rel = t - WK_OFF; }
    else if (t < WO_OFF) { W = Wv; rel = t - WV_OFF; }
    else if (t < W1_OFF) { W = Wo; rel = t - WO_OFF; }
    else if (t < W2_OFF) { W = W1; rel = t - W1_OFF; n1024 = true; }
    else                 { W = W2; rel = t - W2_OFF; }
    int N = n1024 ? 1024 : 512;
    int k2 = n1024 ? (rel >> 10) : (rel >> 9);
    int n  = rel & (N - 1);
    g_wh[t] = hipair(W[(size_t)(2 * k2) * N + n], W[(size_t)(2 * k2 + 1) * N + n]);
}

// ---------------- compact input [x; CLS] -> planes only ----------------
__global__ void k_xc(const float* __restrict__ x, const float* __restrict__ cls, int N) {
    int row = blockIdx.x;
    int tid = threadIdx.x;
    const float* src = (row < N) ? (x + (size_t)row * D512)
                                 : (cls + (size_t)(row - N) * D512);
    float4 v = ((const float4*)src)[tid];
    unsigned h0, l0, h1, l1;
    splitpair(v.x, v.y, h0, l0);
    splitpair(v.z, v.w, h1, l1);
    size_t p = (size_t)row * 256 + 2 * tid;
    g_xch[p] = h0; g_xch[p + 1] = h1;
    g_xcl[p] = l0; g_xcl[p + 1] = l1;
}

// ---------------- pipelined 2-term fp16 GEMM (2-stage, one sync/chunk) ----------------
// A planes hi+lo [M][K/2] u32, B hi plane pre-paired [K/2][N] u32.
// C = (Ah+Al)·Bh + bias [+res] [relu]; 128x128 tile, K-chunk 32.
// Residual row select: row < resN -> resA[row], else resB[row-resN] (both stride N).
#define STGU 7296                 // A 2*2560 + B 2176
#define A_LO 2560
#define B_HI 5120
#define GEMM_SMEM_BYTES (2 * STGU * 4)   // 58368

template<bool RELU, bool HASRES, bool WF32, bool WPL>
__device__ __forceinline__ void gemm_core(
    const unsigned* __restrict__ Ah, const unsigned* __restrict__ Al,
    const unsigned* __restrict__ Bh,
    const float* __restrict__ bias,
    const float* __restrict__ resA, const float* __restrict__ resB, int resN,
    float* __restrict__ C, unsigned* __restrict__ CPh, unsigned* __restrict__ CPl,
    int M, int N, int K)
{
    extern __shared__ unsigned sm[];
    const int Ku = K >> 1;
    int tid = threadIdx.x, lane = tid & 31, warp = tid >> 5;
    int wm = warp >> 2, wn = warp & 3;
    int brow = blockIdx.y * 128, bcol = blockIdx.x * 128;
    unsigned smb = (unsigned)__cvta_generic_to_shared(sm);

    float acc[4][4][4];
#pragma unroll
    for (int mt = 0; mt < 4; mt++)
#pragma unroll
        for (int nt = 0; nt < 4; nt++)
#pragma unroll
            for (int i = 0; i < 4; i++) acc[mt][nt][i] = 0.f;

    int arow = tid >> 2, aq = tid & 3;
    int bk2  = tid >> 5, bq = tid & 31;
    int ag0 = brow + arow, ag1 = ag0 + 64;
    int as0 = (ag0 < M) ? 16 : 0, as1 = (ag1 < M) ? 16 : 0;
    const unsigned* Ar0h = Ah + (size_t)((ag0 < M) ? ag0 : 0) * Ku + aq * 4;
    const unsigned* Ar1h = Ah + (size_t)((ag1 < M) ? ag1 : 0) * Ku + aq * 4;
    const unsigned* Ar0l = Al + (size_t)((ag0 < M) ? ag0 : 0) * Ku + aq * 4;
    const unsigned* Ar1l = Al + (size_t)((ag1 < M) ? ag1 : 0) * Ku + aq * 4;
    const unsigned* B0h = Bh + (size_t)bk2 * N + bcol + bq * 4;
    const unsigned* B1h = Bh + (size_t)(bk2 + 8) * N + bcol + bq * 4;
    unsigned dA0 = smb + 4 * (arow * 20 + aq * 4);
    unsigned dA1 = smb + 4 * ((arow + 64) * 20 + aq * 4);
    unsigned dB0 = smb + 4 * (B_HI + bk2 * 136 + bq * 4);
    unsigned dB1 = smb + 4 * (B_HI + (bk2 + 8) * 136 + bq * 4);

    int nch = K >> 5;

    auto issue = [&](int st, int ch) {
        unsigned so = st * (STGU * 4);
        int ko = ch * 16;
        cpa16(so + dA0,            Ar0h + ko, as0);
        cpa16(so + dA1,            Ar1h + ko, as1);
        cpa16(so + dA0 + A_LO * 4, Ar0l + ko, as0);
        cpa16(so + dA1 + A_LO * 4, Ar1l + ko, as1);
        size_t bko = (size_t)ko * N;
        cpa16(so + dB0, B0h + bko, 16);
        cpa16(so + dB1, B1h + bko, 16);
        CP_COMMIT();
    };

    issue(0, 0);

    int r = lane >> 2, cl = lane & 3;
    int lrow = lane & 15, kq = lane >> 4;
    for (int ch = 0; ch < nch; ch++) {
        CP_WAIT0();
        __syncthreads();
        // safe: the sync above guarantees all warps finished compute(ch-1),
        // whose stage was (ch+1)&1 — the buffer these copies overwrite.
        if (ch + 1 < nch) issue((ch + 1) & 1, ch + 1);
        int base = (ch & 1) * STGU;
#pragma unroll
        for (int s = 0; s < 2; s++) {
            unsigned ah[4][4], al[4][4];
#pragma unroll
            for (int mt = 0; mt < 4; mt++) {
                unsigned ao_ = smb + 4 * (base + (wm * 64 + mt * 16 + lrow) * 20 + s * 8 + kq * 4);
                ldm4(ah[mt], ao_);
                ldm4(al[mt], ao_ + A_LO * 4);
            }
            unsigned bhf[4][2];
#pragma unroll
            for (int nt = 0; nt < 4; nt++) {
                int o = base + B_HI + (s * 8 + cl) * 136 + wn * 32 + nt * 8 + r;
                bhf[nt][0] = sm[o];  bhf[nt][1] = sm[o + 4 * 136];
            }
#pragma unroll
            for (int mt = 0; mt < 4; mt++)
#pragma unroll
                for (int nt = 0; nt < 4; nt++) {
                    mma16(acc[mt][nt], ah[mt], bhf[nt]);
                    mma16(acc[mt][nt], al[mt], bhf[nt]);
                }
        }
    }

#pragma unroll
    for (int mt = 0; mt < 4; mt++) {
        int row0 = brow + wm * 64 + mt * 16 + r;
        int row1 = row0 + 8;
#pragma unroll
        for (int nt = 0; nt < 4; nt++) {
            int col = bcol + wn * 32 + nt * 8 + cl * 2;
            float2 bb = *(const float2*)(bias + col);
            const float* c = acc[mt][nt];
#pragma unroll
            for (int half = 0; half < 2; half++) {
                int row = half ? row1 : row0;
                if (row < M) {
                    float v0 = c[2 * half] + bb.x, v1 = c[2 * half + 1] + bb.y;
                    if (HASRES) {
                        const float* rp = (row < resN)
                            ? resA + (size_t)row * N
                            : resB + (size_t)(row - resN) * N;
                        float2 rv = *(const float2*)(rp + col);
                        v0 += rv.x; v1 += rv.y;
                    }
                    if (RELU) { v0 = fmaxf(v0, 0.f); v1 = fmaxf(v1, 0.f); }
                    if (WF32)
                        *(float2*)(C + (size_t)row * N + col) = make_float2(v0, v1);
                    if (WPL) {
                        unsigned h, l;
                        splitpair(v0, v1, h, l);
                        size_t p = ((size_t)row * N + col) >> 1;
                        CPh[p] = h; CPl[p] = l;
                    }
                }
            }
        }
    }
}

__global__ void __launch_bounds__(256, 2) k_qkv(
    const float* __restrict__ bq, const float* __restrict__ bk,
    const float* __restrict__ bv, int M)
{
    const unsigned* Bh; const float* bias; unsigned* Ph; unsigned* Pl;
    if (blockIdx.z == 0)      { Bh = g_wh + WQ_OFF; bias = bq; Ph = g_qh; Pl = g_ql; }
    else if (blockIdx.z == 1) { Bh = g_wh + WK_OFF; bias = bk; Ph = g_kh; Pl = g_kl; }
    else                      { Bh = g_wh + WV_OFF; bias = bv; Ph = g_vh; Pl = g_vl; }
    gemm_core<false, false, false, true>(g_xch, g_xcl, Bh, bias,
        (const float*)0, (const float*)0, 0, (float*)0, Ph, Pl, M, 512, 512);
}
// residual = compact input rebuilt from x/cls (no fp32 xc buffer)
__global__ void __launch_bounds__(256, 2) k_wo(const float* __restrict__ bo,
                                               const float* __restrict__ x,
                                               const float* __restrict__ cls,
                                               int N, int M) {
    gemm_core<false, true, true, false>(g_ath, g_atl, g_wh + WO_OFF,
        bo, x, cls, N, g_ao, (unsigned*)0, (unsigned*)0, M, 512, 512);
}
__global__ void __launch_bounds__(256, 2) k_ffn1(const float* __restrict__ b1, int M) {
    gemm_core<true, false, false, true>(g_hnh, g_hnl, g_wh + W1_OFF,
        b1, (const float*)0, (const float*)0, 0, (float*)0, g_th, g_tl, M, 1024, 512);
}
__global__ void __launch_bounds__(256, 2) k_ffn2(const float* __restrict__ b2, int M) {
    gemm_core<false, true, true, false>(g_th, g_tl, g_wh + W2_OFF,
        b2, g_hn, (const float*)0, 0x7fffffff, g_f, (unsigned*)0, (unsigned*)0, M, 512, 1024);
}

// ---------------- fp16 flash attention: q-tile 128, 8 warps, double-buffered, one sync/chunk ----------------
// stage (9216 u32): [0..2304) KsHi [2304..4608) KsLo [4608..6912) VsHi [6912..9216) VsLo
#define AST 36
#define A_STG 9216
#define KL_OFF 2304
#define VH_OFF 4608
#define VL_OFF 6912
#define ATT_SMEM (2 * A_STG * 4)   // 73728

__global__ void __launch_bounds__(256) k_attn_mma(int N) {
    extern __shared__ unsigned sm[];
    int b = blockIdx.z, h = blockIdx.y, qt = blockIdx.x;
    int stt = g_starts[b];
    int cnt = g_starts[b + 1] - stt;
    int Lb = cnt + 1;
    if (qt * 128 >= Lb) return;
    int tid = threadIdx.x, lane = tid & 31, warp = tid >> 5;
    int lr = lane >> 2, lc = lane & 3;
    unsigned smb = (unsigned)__cvta_generic_to_shared(sm);

    // ---- stage Q (128 rows) into the FULL stage-0 region: hi at 0, lo at 4608 ----
    {
        int qrow = tid >> 1, qhalf = (tid & 1) * 16;
        int qi = qt * 128 + qrow;
        int grow = (qi < cnt) ? stt + qi : N + b;
        size_t so = (size_t)grow * 256 + h * 32 + qhalf;
        unsigned dQ = smb + 4 * (qrow * AST + qhalf);
#pragma unroll
        for (int i = 0; i < 4; i++) {
            cpa16(dQ + 16 * i,                g_qh + so + 4 * i, 16);
            cpa16(dQ + 16 * i + VH_OFF * 4,   g_ql + so + 4 * i, 16);
        }
        CP_COMMIT(); CP_WAIT0();
    }
    __syncthreads();
    unsigned qh[4][4], qlo[4][4];
    {
        int rq = warp * 16 + lr;
#pragma unroll
        for (int ks = 0; ks < 4; ks++) {
            int c0 = ks * 8 + lc;
            qh[ks][0]  = sm[rq*AST + c0];               qh[ks][1]  = sm[(rq+8)*AST + c0];
            qh[ks][2]  = sm[rq*AST + c0 + 4];           qh[ks][3]  = sm[(rq+8)*AST + c0 + 4];
            qlo[ks][0] = sm[VH_OFF + rq*AST + c0];      qlo[ks][1] = sm[VH_OFF + (rq+8)*AST + c0];
            qlo[ks][2] = sm[VH_OFF + rq*AST + c0 + 4];  qlo[ks][3] = sm[VH_OFF + (rq+8)*AST + c0 + 4];
        }
    }
    __syncthreads();

    // K/V staging: 4 threads per key-row, 8 u32 each
    int ksrow = tid >> 2, ksq = (tid & 3) * 8;
    unsigned dKV = smb + 4 * (ksrow * AST + ksq);
    auto issue = [&](int stg_i, int kt) {
        int ki = kt * 64 + ksrow;
        int grow = (ki < cnt) ? stt + ki : N + b;
        size_t so = (size_t)grow * 256 + h * 32 + ksq;
        unsigned d0 = dKV + stg_i * (A_STG * 4);
#pragma unroll
        for (int i = 0; i < 2; i++) {
            cpa16(d0 + 16 * i,              g_kh + so + 4 * i, 16);
            cpa16(d0 + 16 * i + KL_OFF * 4, g_kl + so + 4 * i, 16);
            cpa16(d0 + 16 * i + VH_OFF * 4, g_vh + so + 4 * i, 16);
            cpa16(d0 + 16 * i + VL_OFF * 4, g_vl + so + 4 * i, 16);
        }
        CP_COMMIT();
    };

    float m0 = -1e30f, m1 = -1e30f, l0 = 0.f, l1 = 0.f;
    float o[8][4];
#pragma unroll
    for (int nt = 0; nt < 8; nt++)
#pragma unroll
        for (int i = 0; i < 4; i++) o[nt][i] = 0.f;

    int vkey = ((lane >> 3) & 1) * 8 + (lane & 7);
    int vdof = (lane >> 4) * 4;

    int nch = (Lb + 63) >> 6;
    issue(0, 0);
    for (int kt = 0; kt < nch; kt++) {
        CP_WAIT0();
        __syncthreads();
        // safe: sync above means all warps finished chunk kt-1, which read stage (kt+1)&1
        if (kt + 1 < nch) issue((kt + 1) & 1, kt + 1);
        int sb = (kt & 1) * A_STG;

        // S = Q K^T (3-term fp16)
        float s[8][4];
#pragma unroll
        for (int nt = 0; nt < 8; nt++) {
            s[nt][0] = s[nt][1] = s[nt][2] = s[nt][3] = 0.f;
#pragma unroll
            for (int ks = 0; ks < 4; ks++) {
                int ko = sb + (nt * 8 + lr) * AST + ks * 8 + lc;
                unsigned bh[2] = {sm[ko], sm[ko + 4]};
                unsigned bl[2] = {sm[ko + KL_OFF], sm[ko + KL_OFF + 4]};
                mma16(s[nt], qh[ks],  bh);
                mma16(s[nt], qlo[ks], bh);
                mma16(s[nt], qh[ks],  bl);
            }
        }
        int cb = kt * 64 + 2 * lc;
#pragma unroll
        for (int nt = 0; nt < 8; nt++) {
            int c0 = cb + nt * 8, c1 = c0 + 1;
            bool v0 = c0 < Lb, v1 = c1 < Lb;
            s[nt][0] = v0 ? s[nt][0] * 0.125f : -1e30f;
            s[nt][1] = v1 ? s[nt][1] * 0.125f : -1e30f;
            s[nt][2] = v0 ? s[nt][2] * 0.125f : -1e30f;
            s[nt][3] = v1 ? s[nt][3] * 0.125f : -1e30f;
        }
        float cm0 = -1e30f, cm1 = -1e30f;
#pragma unroll
        for (int nt = 0; nt < 8; nt++) {
            cm0 = fmaxf(cm0, fmaxf(s[nt][0], s[nt][1]));
            cm1 = fmaxf(cm1, fmaxf(s[nt][2], s[nt][3]));
        }
        cm0 = fmaxf(cm0, __shfl_xor_sync(0xffffffffu, cm0, 1));
        cm0 = fmaxf(cm0, __shfl_xor_sync(0xffffffffu, cm0, 2));
        cm1 = fmaxf(cm1, __shfl_xor_sync(0xffffffffu, cm1, 1));
        cm1 = fmaxf(cm1, __shfl_xor_sync(0xffffffffu, cm1, 2));
        float mn0 = fmaxf(m0, cm0), mn1 = fmaxf(m1, cm1);
        float corr0 = __expf(m0 - mn0), corr1 = __expf(m1 - mn1);
        m0 = mn0; m1 = mn1;

        float sum0 = 0.f, sum1 = 0.f;
        unsigned pah[4][4], pal[4][4];
#pragma unroll
        for (int nt = 0; nt < 8; nt++) {
            float p0 = __expf(s[nt][0] - m0), p1 = __expf(s[nt][1] - m0);
            float p2 = __expf(s[nt][2] - m1), p3 = __expf(s[nt][3] - m1);
            sum0 += p0 + p1; sum1 += p2 + p3;
            unsigned h01, l01, h23, l23;
            splitpair(p0, p1, h01, l01);
            splitpair(p2, p3, h23, l23);
            int kq = nt >> 1, sl = (nt & 1) * 2;
            pah[kq][sl] = h01; pah[kq][sl + 1] = h23;
            pal[kq][sl] = l01; pal[kq][sl + 1] = l23;
        }
        sum0 += __shfl_xor_sync(0xffffffffu, sum0, 1);
        sum0 += __shfl_xor_sync(0xffffffffu, sum0, 2);
        sum1 += __shfl_xor_sync(0xffffffffu, sum1, 1);
        sum1 += __shfl_xor_sync(0xffffffffu, sum1, 2);
        l0 = l0 * corr0 + sum0;
        l1 = l1 * corr1 + sum1;
#pragma unroll
        for (int nt = 0; nt < 8; nt++) {
            o[nt][0] *= corr0; o[nt][1] *= corr0;
            o[nt][2] *= corr1; o[nt][3] *= corr1;
        }
        // O += P V (3-term) via ldmatrix.x4.trans
#pragma unroll
        for (int kq = 0; kq < 4; kq++) {
#pragma unroll
            for (int ntp = 0; ntp < 4; ntp++) {
                unsigned va = smb + 4 * (sb + VH_OFF + (kq * 16 + vkey) * AST + ntp * 8 + vdof);
                unsigned dh_[4], dl_[4];
                ldm4t(dh_, va);
                ldm4t(dl_, va + (VL_OFF - VH_OFF) * 4);
                unsigned bh01[2] = {dh_[0], dh_[1]}, bh23[2] = {dh_[2], dh_[3]};
                unsigned bl01[2] = {dl_[0], dl_[1]}, bl23[2] = {dl_[2], dl_[3]};
                mma16(o[2*ntp],     pah[kq], bh01);
                mma16(o[2*ntp],     pal[kq], bh01);
                mma16(o[2*ntp],     pah[kq], bl01);
                mma16(o[2*ntp + 1], pah[kq], bh23);
                mma16(o[2*ntp + 1], pal[kq], bh23);
                mma16(o[2*ntp + 1], pah[kq], bl23);
            }
        }
    }

    float inv0 = 1.f / l0, inv1 = 1.f / l1;
    int q0 = qt * 128 + warp * 16 + lr;
    int q1 = q0 + 8;
    if (q0 < Lb) {
        int gr = (q0 < cnt) ? stt + q0 : N + b;
        size_t p = (size_t)gr * 256 + h * 32 + lc;
#pragma unroll
        for (int nt = 0; nt < 8; nt++) {
            unsigned hh, ll;
            splitpair(o[nt][0] * inv0, o[nt][1] * inv0, hh, ll);
            g_ath[p + nt * 4] = hh; g_atl[p + nt * 4] = ll;
        }
    }
    if (q1 < Lb) {
        int gr = (q1 < cnt) ? stt + q1 : N + b;
        size_t p = (size_t)gr * 256 + h * 32 + lc;
#pragma unroll
        for (int nt = 0; nt < 8; nt++) {
            unsigned hh, ll;
            splitpair(o[nt][2] * inv1, o[nt][3] * inv1, hh, ll);
            g_ath[p + nt * 4] = hh; g_atl[p + nt * 4] = ll;
        }
    }
}

// ---------------- LayerNorm ----------------
template<bool PLANES>
__device__ __forceinline__ void row_ln(const float* __restrict__ src,
                                       const float* __restrict__ gam,
                                       const float* __restrict__ bet,
                                       float* __restrict__ dst,
                                       unsigned* __restrict__ ph,
                                       unsigned* __restrict__ pl,
                                       int row) {
    int tid = threadIdx.x;
    float4 v = ((const float4*)src)[tid];
    float s  = v.x + v.y + v.z + v.w;
    float ss = v.x*v.x + v.y*v.y + v.z*v.z + v.w*v.w;
#pragma unroll
    for (int off = 16; off; off >>= 1) {
        s  += __shfl_xor_sync(0xffffffffu, s,  off);
        ss += __shfl_xor_sync(0xffffffffu, ss, off);
    }
    __shared__ float sh[4][2];
    int w = tid >> 5;
    if ((tid & 31) == 0) { sh[w][0] = s; sh[w][1] = ss; }
    __syncthreads();
    s  = sh[0][0] + sh[1][0] + sh[2][0] + sh[3][0];
    ss = sh[0][1] + sh[1][1] + sh[2][1] + sh[3][1];
    float mean = s * (1.f / 512.f);
    float var  = ss * (1.f / 512.f) - mean * mean;
    float rr = rsqrtf(var + 1e-5f);
    float4 gg = ((const float4*)gam)[tid];
    float4 bb = ((const float4*)bet)[tid];
    float4 out;
    out.x = (v.x - mean) * rr * gg.x + bb.x;
    out.y = (v.y - mean) * rr * gg.y + bb.y;
    out.z = (v.z - mean) * rr * gg.z + bb.z;
    out.w = (v.w - mean) * rr * gg.w + bb.w;
    ((float4*)dst)[tid] = out;
    if (PLANES) {
        unsigned h0, l0, h1, l1;
        splitpair(out.x, out.y, h0, l0);
        splitpair(out.z, out.w, h1, l1);
        size_t p = (size_t)row * 256 + 2 * tid;
        ph[p] = h0; ph[p + 1] = h1;
        pl[p] = l0; pl[p + 1] = l1;
    }
}

__global__ void k_ln0(const float* __restrict__ gam, const float* __restrict__ bet) {
    int row = blockIdx.x;
    row_ln<true>(g_ao + (size_t)row * D512, gam, bet,
                 g_hn + (size_t)row * D512, g_hnh, g_hnl, row);
}
__global__ void k_ln1(const float* __restrict__ gam, const float* __restrict__ bet,
                      float* __restrict__ out) {
    int row = blockIdx.x;
    row_ln<false>(g_f + (size_t)row * D512, gam, bet,
                  out + (size_t)row * D512, (unsigned*)0, (unsigned*)0, row);
}

// ---------------- launch ----------------
extern "C" void kernel_launch(void* const* d_in, const int* in_sizes, int n_in,
                              void* d_out, int out_size) {
    const float* x     = (const float*)d_in[0];
    const int*   batch = (const int*)  d_in[1];
    const float* cls   = (const float*)d_in[2];
    const float* Wq = (const float*)d_in[3];  const float* bq = (const float*)d_in[4];
    const float* Wk = (const float*)d_in[5];  const float* bk = (const float*)d_in[6];
    const float* Wv = (const float*)d_in[7];  const float* bv = (const float*)d_in[8];
    const float* Wo = (const float*)d_in[9];  const float* bo = (const float*)d_in[10];
    const float* W1 = (const float*)d_in[11]; const float* b1 = (const float*)d_in[12];
    const float* W2 = (const float*)d_in[13]; const float* b2 = (const float*)d_in[14];
    const float* g0 = (const float*)d_in[15]; const float* be0 = (const float*)d_in[16];
    const float* ga1 = (const float*)d_in[17]; const float* be1 = (const float*)d_in[18];

    int N = in_sizes[0] / D512;      // 16384
    int B = in_sizes[2] / D512;      // 32
    int M2 = N + B;                  // 16416

    cudaFuncSetAttribute(k_qkv,  cudaFuncAttributeMaxDynamicSharedMemorySize, GEMM_SMEM_BYTES);
    cudaFuncSetAttribute(k_wo,   cudaFuncAttributeMaxDynamicSharedMemorySize, GEMM_SMEM_BYTES);
    cudaFuncSetAttribute(k_ffn1, cudaFuncAttributeMaxDynamicSharedMemorySize, GEMM_SMEM_BYTES);
    cudaFuncSetAttribute(k_ffn2, cudaFuncAttributeMaxDynamicSharedMemorySize, GEMM_SMEM_BYTES);
    cudaFuncSetAttribute(k_attn_mma, cudaFuncAttributeMaxDynamicSharedMemorySize, ATT_SMEM);

    k_starts<<<1, 64>>>(batch, N, B);
    k_splitW<<<WTOT / 256, 256>>>(Wq, Wk, Wv, Wo, W1, W2);
    k_xc<<<M2, 128>>>(x, cls, N);

    int my = (M2 + 127) / 128;       // 129
    k_qkv<<<dim3(4, my, 3), 256, GEMM_SMEM_BYTES>>>(bq, bk, bv, M2);

    k_attn_mma<<<dim3(7, NH, B), 256, ATT_SMEM>>>(N);

    k_wo<<<dim3(4, my), 256, GEMM_SMEM_BYTES>>>(bo, x, cls, N, M2);

    k_ln0<<<M2, 128>>>(g0, be0);

    k_ffn1<<<dim3(8, my), 256, GEMM_SMEM_BYTES>>>(b1, M2);
    k_ffn2<<<dim3(4, my), 256, GEMM_SMEM_BYTES>>>(b2, M2);

    k_ln1<<<M2, 128>>>(ga1, be1, (float*)d_out);
}